// round 5
// baseline (speedup 1.0000x reference)
#include <cuda_runtime.h>
#include <cuda_bf16.h>
#include <math.h>
#include <stdint.h>

// ---------------- problem constants ----------------
#define BZ    8
#define HH    56
#define WW    56
#define HWP   3136
#define RR    25088       // BZ*HWP rows
#define C0N   256
#define C1N   512
#define C2N   1024
#define CIN   1794
#define DOUT  448
#define NC    3136

#define KBP   1856        // gemmB K padded (29*64)
#define XSTR  (2*KBP)     // hi plane + lo plane
#define KCP   448         // gemmC K (7*64)
#define PSTR  (2*KCP)

#define SEG_B (KBP/64)    // 29
#define SEG_C (KCP/64)    // 7
#define NCH_B (3*SEG_B)   // 87
#define NCH_C (3*SEG_C)   // 21
#define NTILE 224
#define NT_C  (NC/NTILE)  // 14

// smem layout (bytes): A bufs 128x72 halves, B bufs 224x72 halves
#define ABUF0 0
#define ABUF1 18432
#define BBUF0 36864
#define BBUF1 69120
#define AUXOF 101376
#define SMEM_SZ 104448

// ---------------- scratch ----------------
__device__ float g_pool1[BZ * C1N * 28 * 28];
__device__ float g_pool2[BZ * C2N * 14 * 14];
__device__ float g_feat2[RR];
__device__ float g_cent2[NC];
__device__ __align__(16) unsigned short gXt[(size_t)RR * XSTR];
__device__ __align__(16) unsigned short gWt[(size_t)DOUT * XSTR];
__device__ __align__(16) unsigned short gPhiT[(size_t)RR * PSTR];
__device__ __align__(16) unsigned short gCt[(size_t)NC * PSTR];

// ---------------- helpers ----------------
__device__ __forceinline__ uint32_t smem_u32(const void* p) {
    uint32_t a;
    asm("{ .reg .u64 t; cvta.to.shared.u64 t, %1; cvt.u32.u64 %0, t; }" : "=r"(a) : "l"(p));
    return a;
}
__device__ __forceinline__ void cp16(uint32_t dst, const void* src) {
    asm volatile("cp.async.cg.shared.global [%0], [%1], 16;" :: "r"(dst), "l"(src) : "memory");
}
#define CP_COMMIT() asm volatile("cp.async.commit_group;" ::: "memory")
#define CP_WAIT1()  asm volatile("cp.async.wait_group 1;" ::: "memory")
#define CP_WAIT0()  asm volatile("cp.async.wait_group 0;" ::: "memory")

__device__ __forceinline__ uint32_t lds32(const unsigned short* p) {
    return *(const uint32_t*)p;
}
__device__ __forceinline__ void mma16816(float* c, const uint32_t* a, uint32_t b0, uint32_t b1) {
    asm volatile(
        "mma.sync.aligned.m16n8k16.row.col.f32.bf16.bf16.f32 "
        "{%0,%1,%2,%3},{%4,%5,%6,%7},{%8,%9},{%0,%1,%2,%3};"
        : "+f"(c[0]), "+f"(c[1]), "+f"(c[2]), "+f"(c[3])
        : "r"(a[0]), "r"(a[1]), "r"(a[2]), "r"(a[3]), "r"(b0), "r"(b1));
}

__device__ __forceinline__ unsigned short f2bf(float x) {
    __nv_bfloat16 h = __float2bfloat16(x);
    unsigned short u; memcpy(&u, &h, 2); return u;
}
__device__ __forceinline__ float bf2f(unsigned short u) {
    __nv_bfloat16 h; memcpy(&h, &u, 2); return __bfloat162float(h);
}
__device__ __forceinline__ void ins3(float v, float& a, float& b, float& c) {
    if (v < c) {
        if (v < b) { c = b; if (v < a) { b = a; a = v; } else b = v; }
        else c = v;
    }
}
__device__ __forceinline__ void merge_shfl(float& a, float& b, float& c, int mask) {
    float x = __shfl_xor_sync(0xFFFFFFFFu, a, mask);
    float y = __shfl_xor_sync(0xFFFFFFFFu, b, mask);
    float z = __shfl_xor_sync(0xFFFFFFFFu, c, mask);
    ins3(x, a, b, c); ins3(y, a, b, c); ins3(z, a, b, c);
}

__device__ __forceinline__ float bilin(const float* __restrict__ ch, int S, float u, float v) {
    int y0 = (int)floorf(u); float fy = u - (float)y0;
    int x0 = (int)floorf(v); float fx = v - (float)x0;
    int y0c = min(max(y0, 0), S - 1);
    int y1c = min(max(y0 + 1, 0), S - 1);
    int x0c = min(max(x0, 0), S - 1);
    int x1c = min(max(x0 + 1, 0), S - 1);
    float a = ch[y0c * S + x0c], b = ch[y0c * S + x1c];
    float c = ch[y1c * S + x0c], d = ch[y1c * S + x1c];
    return (1.f - fy) * ((1.f - fx) * a + fx * b) + fy * ((1.f - fx) * c + fx * d);
}

// ---------------- stage 1: pools for p1/p2 ----------------
__global__ void pool_kernel(const float* __restrict__ in, int total, int S, int which) {
    int idx = blockIdx.x * 256 + threadIdx.x;
    if (idx >= total) return;
    int x = idx % S, y = (idx / S) % S, bc = idx / (S * S);
    const float* p = in + (size_t)bc * S * S;
    float s = 0.f;
    #pragma unroll
    for (int dy = -1; dy <= 1; dy++) {
        int yy = y + dy; if ((unsigned)yy >= (unsigned)S) continue;
        #pragma unroll
        for (int dx = -1; dx <= 1; dx++) {
            int xx = x + dx; if ((unsigned)xx >= (unsigned)S) continue;
            s += p[yy * S + xx];
        }
    }
    (which ? g_pool2 : g_pool1)[idx] = s * (1.f / 9.f);
}

// ---------------- stage 2: weight/center packing ----------------
__global__ void prepW_kernel(const float* __restrict__ w) {
    int idx = blockIdx.x * 256 + threadIdx.x;
    if (idx >= DOUT * KBP) return;
    int o = idx / KBP, k = idx - o * KBP;
    float v = (k < CIN) ? w[o * CIN + k] : 0.f;
    unsigned short h = f2bf(v);
    gWt[(size_t)o * XSTR + k] = h;
    gWt[(size_t)o * XSTR + KBP + k] = f2bf(v - bf2f(h));
}

__global__ void prepC_kernel(const float* __restrict__ Cmat) {
    int idx = blockIdx.x * 256 + threadIdx.x;
    if (idx >= NC * KCP) return;
    int k = idx / NC, n = idx - k * NC;
    float v = Cmat[(size_t)k * NC + n];
    unsigned short h = f2bf(v);
    gCt[(size_t)n * PSTR + k] = h;
    gCt[(size_t)n * PSTR + KCP + k] = f2bf(v - bf2f(h));
}

__global__ void cent2_kernel(const float* __restrict__ Cmat) {
    int gid = blockIdx.x * 256 + threadIdx.x;
    int n = gid >> 3, part = gid & 7;
    if (n >= NC) return;
    float s = 0.f;
    for (int o = part; o < DOUT; o += 8) {
        float v = Cmat[(size_t)o * NC + n];
        s = fmaf(v, v, s);
    }
    s += __shfl_xor_sync(0xFFFFFFFFu, s, 1);
    s += __shfl_xor_sync(0xFFFFFFFFu, s, 2);
    s += __shfl_xor_sync(0xFFFFFFFFu, s, 4);
    if (part == 0) g_cent2[n] = s;
}

// ---------------- stage 3: build X row-major bf16 hi/lo via smem transpose ----------------
__global__ void buildx_kernel(const float* __restrict__ p0) {
    __shared__ float s[64][65];
    int rt0 = blockIdx.x * 64;
    int kt0 = blockIdx.y * 64;
    int tid = threadIdx.x;
    int rr = tid & 63;
    int r = rt0 + rr;
    int b = r / HWP;
    int pix = r - b * HWP;
    int h = pix / WW, w = pix - h * WW;

    #pragma unroll 1
    for (int i = 0; i < 16; i++) {
        int kk = (tid >> 6) * 16 + i;
        int k = kt0 + kk;
        float val;
        if (k < C0N) {
            const float* p = p0 + (size_t)(b * C0N + k) * HWP;
            float acc = 0.f;
            #pragma unroll
            for (int dy = -1; dy <= 1; dy++) {
                int y = h + dy; if ((unsigned)y >= (unsigned)HH) continue;
                #pragma unroll
                for (int dx = -1; dx <= 1; dx++) {
                    int x = w + dx; if ((unsigned)x >= (unsigned)WW) continue;
                    acc += p[y * WW + x];
                }
            }
            val = acc * (1.f / 9.f);
        } else if (k < C0N + C1N) {
            const float* ch = g_pool1 + (size_t)(b * C1N + (k - C0N)) * 784;
            val = bilin(ch, 28, h * 0.5f - 0.25f, w * 0.5f - 0.25f);
        } else if (k < C0N + C1N + C2N) {
            const float* ch = g_pool2 + (size_t)(b * C2N + (k - C0N - C1N)) * 196;
            val = bilin(ch, 14, h * 0.25f - 0.375f, w * 0.25f - 0.375f);
        } else if (k == 1792) {
            val = (float)h * (2.f / 55.f) - 1.f;
        } else if (k == 1793) {
            val = (float)w * (2.f / 55.f) - 1.f;
        } else {
            val = 0.f;
        }
        s[kk][rr] = val;
    }
    __syncthreads();

    #pragma unroll
    for (int it = 0; it < 2; it++) {
        int sg = tid + it * 256;
        int row = sg >> 3, c8 = (sg & 7) * 8;
        unsigned hw[4], lw[4];
        #pragma unroll
        for (int j = 0; j < 8; j += 2) {
            float v0 = s[c8 + j][row], v1 = s[c8 + j + 1][row];
            unsigned short h0 = f2bf(v0), h1 = f2bf(v1);
            unsigned short l0 = f2bf(v0 - bf2f(h0)), l1 = f2bf(v1 - bf2f(h1));
            hw[j >> 1] = (unsigned)h0 | ((unsigned)h1 << 16);
            lw[j >> 1] = (unsigned)l0 | ((unsigned)l1 << 16);
        }
        size_t base = (size_t)(rt0 + row) * XSTR + kt0 + c8;
        *(uint4*)(gXt + base)       = make_uint4(hw[0], hw[1], hw[2], hw[3]);
        *(uint4*)(gXt + base + KBP) = make_uint4(lw[0], lw[1], lw[2], lw[3]);
    }
}

// ==================================================================
// GEMM-B: phi = X * W^T + bias; fused feat2 + bf16 hi/lo store.
// block 128 rows; 2 n-tiles of 224; warp tile 32x112 (m16n8k16).
// ==================================================================
__global__ void __launch_bounds__(256)
gemmB_kernel(const float* __restrict__ bias) {
    extern __shared__ char smc[];
    unsigned short* smh = (unsigned short*)smc;
    uint32_t smb = smem_u32(smc);
    float* sfeat = (float*)(smc + AUXOF);
    int tid = threadIdx.x, wid = tid >> 5, lane = tid & 31;
    int wm = wid & 3, wn = wid >> 2, g = lane >> 2, tg = lane & 3;
    int r0 = blockIdx.x * 128;

    if (tid < 128) sfeat[tid] = 0.f;

    const uint32_t abufs[2] = {smb + ABUF0, smb + ABUF1};
    const uint32_t bbufs[2] = {smb + BBUF0, smb + BBUF1};
    const unsigned short* abufh[2] = {smh + ABUF0 / 2, smh + ABUF1 / 2};
    const unsigned short* bbufh[2] = {smh + BBUF0 / 2, smh + BBUF1 / 2};

    #pragma unroll 1
    for (int nt = 0; nt < 2; nt++) {
        float acc[2][14][4];
        #pragma unroll
        for (int mi = 0; mi < 2; mi++)
            #pragma unroll
            for (int nj = 0; nj < 14; nj++)
                #pragma unroll
                for (int q = 0; q < 4; q++) acc[mi][nj][q] = 0.f;

        // chunk staging lambda
        auto stage = [&](int c, int buf) {
            int seg = c / SEG_B;
            int kb = (c - seg * SEG_B) * 64;
            int pa = (seg == 2) ? KBP : 0;
            int pb = (seg == 1) ? KBP : 0;
            const unsigned short* As = gXt + (size_t)r0 * XSTR + pa + kb;
            const unsigned short* Bs = gWt + (size_t)(nt * NTILE) * XSTR + pb + kb;
            uint32_t ab = abufs[buf], bb = bbufs[buf];
            #pragma unroll
            for (int s = 0; s < 4; s++) {
                int l = tid + s * 256;
                int row = l >> 3, c8 = l & 7;
                cp16(ab + row * 144 + c8 * 16, As + (size_t)row * XSTR + c8 * 8);
            }
            #pragma unroll
            for (int s = 0; s < 7; s++) {
                int l = tid + s * 256;
                int row = l >> 3, c8 = l & 7;
                cp16(bb + row * 144 + c8 * 16, Bs + (size_t)row * XSTR + c8 * 8);
            }
        };

        stage(0, 0);
        CP_COMMIT();

        #pragma unroll 1
        for (int c = 0; c < NCH_B; c++) {
            int buf = c & 1;
            if (c + 1 < NCH_B) {
                stage(c + 1, buf ^ 1);
                CP_COMMIT();
                CP_WAIT1();
            } else {
                CP_WAIT0();
            }
            __syncthreads();
            const unsigned short* Ab = abufh[buf];
            const unsigned short* Bb = bbufh[buf];
            #pragma unroll
            for (int ks = 0; ks < 4; ks++) {
                int k0 = ks * 16 + tg * 2;
                uint32_t a[2][4];
                #pragma unroll
                for (int mi = 0; mi < 2; mi++) {
                    const unsigned short* ap = Ab + (wm * 32 + mi * 16 + g) * 72 + k0;
                    a[mi][0] = lds32(ap);
                    a[mi][1] = lds32(ap + 8 * 72);
                    a[mi][2] = lds32(ap + 8);
                    a[mi][3] = lds32(ap + 8 * 72 + 8);
                }
                #pragma unroll
                for (int nj = 0; nj < 14; nj++) {
                    const unsigned short* bp = Bb + (wn * 112 + nj * 8 + g) * 72 + k0;
                    uint32_t b0 = lds32(bp), b1 = lds32(bp + 8);
                    mma16816(acc[0][nj], a[0], b0, b1);
                    mma16816(acc[1][nj], a[1], b0, b1);
                }
            }
            __syncthreads();
        }

        // epilogue: bias + feat2 + bf16 hi/lo split store (register-resident)
        #pragma unroll
        for (int mi = 0; mi < 2; mi++) {
            #pragma unroll
            for (int rh = 0; rh < 2; rh++) {
                int rl = wm * 32 + mi * 16 + rh * 8 + g;
                size_t r = (size_t)r0 + rl;
                float fpart = 0.f;
                #pragma unroll
                for (int nj = 0; nj < 14; nj++) {
                    int col = nt * NTILE + wn * 112 + nj * 8 + tg * 2;
                    float2 bb = __ldg((const float2*)(bias + col));
                    float v0 = acc[mi][nj][rh * 2]     + bb.x;
                    float v1 = acc[mi][nj][rh * 2 + 1] + bb.y;
                    fpart = fmaf(v0, v0, fpart);
                    fpart = fmaf(v1, v1, fpart);
                    unsigned short h0 = f2bf(v0), h1 = f2bf(v1);
                    unsigned short l0 = f2bf(v0 - bf2f(h0)), l1 = f2bf(v1 - bf2f(h1));
                    *(uint32_t*)(gPhiT + r * PSTR + col) = (uint32_t)h0 | ((uint32_t)h1 << 16);
                    *(uint32_t*)(gPhiT + r * PSTR + KCP + col) = (uint32_t)l0 | ((uint32_t)l1 << 16);
                }
                fpart += __shfl_xor_sync(0xFFFFFFFFu, fpart, 1);
                fpart += __shfl_xor_sync(0xFFFFFFFFu, fpart, 2);
                if (tg == 0) atomicAdd(&sfeat[rl], fpart);
            }
        }
        __syncthreads();
    }

    if (tid < 128) g_feat2[r0 + tid] = sfeat[tid];
}

// ==================================================================
// GEMM-C: streaming top-3 over centers, softmin score.
// block 128 rows; 14 n-tiles of 224; warp tile 32x112.
// ==================================================================
__global__ void __launch_bounds__(256)
gemmC_kernel(float* __restrict__ out) {
    extern __shared__ char smc[];
    unsigned short* smh = (unsigned short*)smc;
    uint32_t smb = smem_u32(smc);
    float* trip = (float*)(smc + AUXOF);   // [128][2][3]
    int tid = threadIdx.x, wid = tid >> 5, lane = tid & 31;
    int wm = wid & 3, wn = wid >> 2, g = lane >> 2, tg = lane & 3;
    int r0 = blockIdx.x * 128;

    const uint32_t abufs[2] = {smb + ABUF0, smb + ABUF1};
    const uint32_t bbufs[2] = {smb + BBUF0, smb + BBUF1};
    const unsigned short* abufh[2] = {smh + ABUF0 / 2, smh + ABUF1 / 2};
    const unsigned short* bbufh[2] = {smh + BBUF0 / 2, smh + BBUF1 / 2};

    const float BIG = 3.4e38f;
    float t3[4][3];
    #pragma unroll
    for (int i = 0; i < 4; i++) { t3[i][0] = BIG; t3[i][1] = BIG; t3[i][2] = BIG; }

    #pragma unroll 1
    for (int nt = 0; nt < NT_C; nt++) {
        int n0 = nt * NTILE;
        float acc[2][14][4];
        #pragma unroll
        for (int mi = 0; mi < 2; mi++)
            #pragma unroll
            for (int nj = 0; nj < 14; nj++)
                #pragma unroll
                for (int q = 0; q < 4; q++) acc[mi][nj][q] = 0.f;

        auto stage = [&](int c, int buf) {
            int seg = c / SEG_C;
            int kb = (c - seg * SEG_C) * 64;
            int pa = (seg == 2) ? KCP : 0;
            int pb = (seg == 1) ? KCP : 0;
            const unsigned short* As = gPhiT + (size_t)r0 * PSTR + pa + kb;
            const unsigned short* Bs = gCt + (size_t)n0 * PSTR + pb + kb;
            uint32_t ab = abufs[buf], bb = bbufs[buf];
            #pragma unroll
            for (int s = 0; s < 4; s++) {
                int l = tid + s * 256;
                int row = l >> 3, c8 = l & 7;
                cp16(ab + row * 144 + c8 * 16, As + (size_t)row * PSTR + c8 * 8);
            }
            #pragma unroll
            for (int s = 0; s < 7; s++) {
                int l = tid + s * 256;
                int row = l >> 3, c8 = l & 7;
                cp16(bb + row * 144 + c8 * 16, Bs + (size_t)row * PSTR + c8 * 8);
            }
        };

        stage(0, 0);
        CP_COMMIT();

        #pragma unroll 1
        for (int c = 0; c < NCH_C; c++) {
            int buf = c & 1;
            if (c + 1 < NCH_C) {
                stage(c + 1, buf ^ 1);
                CP_COMMIT();
                CP_WAIT1();
            } else {
                CP_WAIT0();
            }
            __syncthreads();
            const unsigned short* Ab = abufh[buf];
            const unsigned short* Bb = bbufh[buf];
            #pragma unroll
            for (int ks = 0; ks < 4; ks++) {
                int k0 = ks * 16 + tg * 2;
                uint32_t a[2][4];
                #pragma unroll
                for (int mi = 0; mi < 2; mi++) {
                    const unsigned short* ap = Ab + (wm * 32 + mi * 16 + g) * 72 + k0;
                    a[mi][0] = lds32(ap);
                    a[mi][1] = lds32(ap + 8 * 72);
                    a[mi][2] = lds32(ap + 8);
                    a[mi][3] = lds32(ap + 8 * 72 + 8);
                }
                #pragma unroll
                for (int nj = 0; nj < 14; nj++) {
                    const unsigned short* bp = Bb + (wn * 112 + nj * 8 + g) * 72 + k0;
                    uint32_t b0 = lds32(bp), b1 = lds32(bp + 8);
                    mma16816(acc[0][nj], a[0], b0, b1);
                    mma16816(acc[1][nj], a[1], b0, b1);
                }
            }
            __syncthreads();
        }

        // top-3 update from registers: key = |c|^2 - 2*dot
        #pragma unroll
        for (int mi = 0; mi < 2; mi++) {
            #pragma unroll
            for (int rh = 0; rh < 2; rh++) {
                int idx = mi * 2 + rh;
                #pragma unroll
                for (int nj = 0; nj < 14; nj++) {
                    int col = n0 + wn * 112 + nj * 8 + tg * 2;
                    float2 c2 = __ldg((const float2*)(g_cent2 + col));
                    ins3(c2.x - 2.f * acc[mi][nj][rh * 2],     t3[idx][0], t3[idx][1], t3[idx][2]);
                    ins3(c2.y - 2.f * acc[mi][nj][rh * 2 + 1], t3[idx][0], t3[idx][1], t3[idx][2]);
                }
            }
        }
    }

    // merge across tg lanes (same rows), then across the 2 n-warps via smem
    #pragma unroll
    for (int idx = 0; idx < 4; idx++) {
        merge_shfl(t3[idx][0], t3[idx][1], t3[idx][2], 1);
        merge_shfl(t3[idx][0], t3[idx][1], t3[idx][2], 2);
    }
    if (tg == 0) {
        #pragma unroll
        for (int idx = 0; idx < 4; idx++) {
            int rl = wm * 32 + (idx >> 1) * 16 + (idx & 1) * 8 + g;
            trip[rl * 6 + wn * 3 + 0] = t3[idx][0];
            trip[rl * 6 + wn * 3 + 1] = t3[idx][1];
            trip[rl * 6 + wn * 3 + 2] = t3[idx][2];
        }
    }
    __syncthreads();

    if (tid < 128) {
        float k0 = trip[tid * 6 + 0], k1 = trip[tid * 6 + 1], k2 = trip[tid * 6 + 2];
        ins3(trip[tid * 6 + 3], k0, k1, k2);
        ins3(trip[tid * 6 + 4], k0, k1, k2);
        ins3(trip[tid * 6 + 5], k0, k1, k2);
        float f2 = g_feat2[r0 + tid];
        float d0 = sqrtf(fmaxf(f2 + k0, 0.f));
        float d1 = sqrtf(fmaxf(f2 + k1, 0.f));
        float d2 = sqrtf(fmaxf(f2 + k2, 0.f));
        float s = 1.f / (1.f + expf(d0 - d1) + expf(d0 - d2));
        out[r0 + tid] = d0 * s;
    }
}

// ---------------- launch ----------------
extern "C" void kernel_launch(void* const* d_in, const int* in_sizes, int n_in,
                              void* d_out, int out_size) {
    (void)in_sizes; (void)n_in; (void)out_size;
    const float* p0     = (const float*)d_in[0];
    const float* p1     = (const float*)d_in[1];
    const float* p2     = (const float*)d_in[2];
    const float* conv_w = (const float*)d_in[3];
    const float* conv_b = (const float*)d_in[4];
    const float* Cmat   = (const float*)d_in[5];
    float* out = (float*)d_out;

    {
        int t1 = BZ * C1N * 28 * 28;
        pool_kernel<<<(t1 + 255) / 256, 256>>>(p1, t1, 28, 0);
        int t2 = BZ * C2N * 14 * 14;
        pool_kernel<<<(t2 + 255) / 256, 256>>>(p2, t2, 14, 1);
    }
    prepW_kernel<<<(DOUT * KBP + 255) / 256, 256>>>(conv_w);
    prepC_kernel<<<(NC * KCP + 255) / 256, 256>>>(Cmat);
    cent2_kernel<<<(NC * 8 + 255) / 256, 256>>>(Cmat);
    {
        dim3 grid(RR / 64, KBP / 64);
        buildx_kernel<<<grid, 256>>>(p0);
    }
    {
        cudaFuncSetAttribute(gemmB_kernel, cudaFuncAttributeMaxDynamicSharedMemorySize, SMEM_SZ);
        gemmB_kernel<<<RR / 128, 256, SMEM_SZ>>>(conv_b);
    }
    {
        cudaFuncSetAttribute(gemmC_kernel, cudaFuncAttributeMaxDynamicSharedMemorySize, SMEM_SZ);
        gemmC_kernel<<<RR / 128, 256, SMEM_SZ>>>(out);
    }
}